// round 11
// baseline (speedup 1.0000x reference)
#include <cuda_runtime.h>
#include <cuda_fp16.h>
#include <cstdint>
#include <cstddef>

#define NTOK 4096
#define HDIM 1024
#define IDIM 4096
#define NEXP 8

// ------------------------- scratch (static device, no allocs) -------------------------
__device__ __half g_x[(size_t)NTOK * HDIM];
__device__ __half g_w1[(size_t)NEXP * IDIM * HDIM];
__device__ __half g_w2[(size_t)NEXP * HDIM * IDIM];
__device__ __half g_mid[(size_t)NEXP * NTOK * IDIM];     // per-expert gelu output
__device__ float g_part[(size_t)NEXP * NTOK * HDIM];     // per-expert weighted partials
__device__ float g_probs[NTOK * NEXP];

// ------------------------- PTX helpers -------------------------
__device__ __forceinline__ uint32_t smem_u32(const void* p) {
    uint32_t a;
    asm("{ .reg .u64 t; cvta.to.shared.u64 t, %1; cvt.u32.u64 %0, t; }" : "=r"(a) : "l"(p));
    return a;
}

__device__ __forceinline__ void cp_async16(uint32_t smem, const void* g) {
    asm volatile("cp.async.cg.shared.global [%0], [%1], 16;\n" :: "r"(smem), "l"(g));
}

// swizzle for 128B rows: off = row*128 + (colbyte ^ ((row&7)<<4))
__device__ __forceinline__ uint32_t swz_row(uint32_t row, uint32_t colbyte) {
    return row * 128u + (colbyte ^ ((row & 7u) << 4));
}

__device__ __forceinline__ void ldsm_x4(uint32_t (&r)[4], uint32_t addr) {
    asm volatile("ldmatrix.sync.aligned.m8n8.x4.shared.b16 {%0,%1,%2,%3}, [%4];"
                 : "=r"(r[0]), "=r"(r[1]), "=r"(r[2]), "=r"(r[3]) : "r"(addr));
}

__device__ __forceinline__ void mma16816(float (&d)[4], const uint32_t (&a)[4],
                                         const uint32_t (&b)[2]) {
    asm volatile(
        "mma.sync.aligned.m16n8k16.row.col.f32.f16.f16.f32 "
        "{%0,%1,%2,%3}, {%4,%5,%6,%7}, {%8,%9}, {%0,%1,%2,%3};"
        : "+f"(d[0]), "+f"(d[1]), "+f"(d[2]), "+f"(d[3])
        : "r"(a[0]), "r"(a[1]), "r"(a[2]), "r"(a[3]), "r"(b[0]), "r"(b[1]));
}

// ------------------------- merged convert kernel: fp32 -> fp16 (x, W1, W2) ---------------
__global__ void moe_cvt3_kernel(const float* __restrict__ s0, __half* __restrict__ d0, size_t n0,
                                const float* __restrict__ s1, __half* __restrict__ d1, size_t n1,
                                const float* __restrict__ s2, __half* __restrict__ d2, size_t n2) {
    size_t total = n0 + n1 + n2;
    size_t i = (size_t)blockIdx.x * blockDim.x + threadIdx.x;
    size_t stride = (size_t)gridDim.x * blockDim.x;
    for (; i < total; i += stride) {
        const float* src;
        __half* dst;
        size_t j = i;
        if (j < n0) { src = s0; dst = d0; }
        else if (j < n0 + n1) { j -= n0; src = s1; dst = d1; }
        else { j -= n0 + n1; src = s2; dst = d2; }
        const float4* s = (const float4*)(src + j * 8);
        float4 a = s[0], b = s[1];
        union { __half h[8]; uint4 u; } H;
        H.h[0] = __float2half_rn(a.x); H.h[1] = __float2half_rn(a.y);
        H.h[2] = __float2half_rn(a.z); H.h[3] = __float2half_rn(a.w);
        H.h[4] = __float2half_rn(b.x); H.h[5] = __float2half_rn(b.y);
        H.h[6] = __float2half_rn(b.z); H.h[7] = __float2half_rn(b.w);
        *(uint4*)(dst + j * 8) = H.u;
    }
}

// ------------------------- router: logits -> softmax -> sort desc -------------------------
__global__ void moe_router_kernel(const float* __restrict__ hs, const float* __restrict__ Wr,
                                  float* __restrict__ probs) {
    int warp = threadIdx.x >> 5, lane = threadIdx.x & 31;
    int n = blockIdx.x * 4 + warp;
    if (n >= NTOK) return;
    const float* x = hs + (size_t)n * HDIM;
    float acc[NEXP];
    #pragma unroll
    for (int e = 0; e < NEXP; ++e) acc[e] = 0.f;
    for (int j = lane; j < HDIM; j += 32) {
        float xv = x[j];
        #pragma unroll
        for (int e = 0; e < NEXP; ++e) acc[e] += xv * Wr[e * HDIM + j];
    }
    #pragma unroll
    for (int off = 16; off; off >>= 1) {
        #pragma unroll
        for (int e = 0; e < NEXP; ++e)
            acc[e] += __shfl_down_sync(0xffffffffu, acc[e], off);
    }
    if (lane == 0) {
        float m = acc[0];
        #pragma unroll
        for (int e = 1; e < NEXP; ++e) m = fmaxf(m, acc[e]);
        float s = 0.f, p[NEXP];
        #pragma unroll
        for (int e = 0; e < NEXP; ++e) { p[e] = expf(acc[e] - m); s += p[e]; }
        float inv = 1.f / s;
        #pragma unroll
        for (int e = 0; e < NEXP; ++e) p[e] *= inv;
        #pragma unroll
        for (int i = 1; i < NEXP; ++i) {
            float key = p[i];
            int j = i - 1;
            while (j >= 0 && p[j] < key) { p[j + 1] = p[j]; --j; }
            p[j + 1] = key;
        }
        #pragma unroll
        for (int e = 0; e < NEXP; ++e) probs[n * NEXP + e] = p[e];
    }
}

// ------------------------- fp16 GEMM, 128x128 tile, 8 warps of 64x32 ---------------------
// 256 threads, warp grid 2(M) x 4(N), warp tile 64x32 -> acc 64 regs/thread.
// K-chunk 64, 3-stage cp.async, 1 sync/chunk, 2 CTA/SM (16 warps/SM = 4/SMSP).
// MODE 0: K=HDIM;  A=x, B=w1[z];  mid[z] = fp16(gelu(D))
// MODE 1: K=IDIM;  A=mid[z], B=w2[z];  part[z] = prob[m,z] * D   (no RMW)
template <int MODE>
__global__ void __launch_bounds__(256, 2) moe_gemm() {
    constexpr int K = (MODE == 0) ? HDIM : IDIM;
    constexpr int MT = 128;
    constexpr int NT = 128;
    constexpr int A_BYTES = MT * 128;          // 16384
    constexpr int B_BYTES = NT * 128;          // 16384
    constexpr int STAGE = A_BYTES + B_BYTES;   // 32768
    constexpr int NSTG = 3;
    constexpr int NC = K / 64;

    extern __shared__ char dsm[];

    const int tid = threadIdx.x, wid = tid >> 5, lane = tid & 31;
    const int m0 = blockIdx.x * MT;
    const int n0 = blockIdx.y * NT;
    const int ez = blockIdx.z;

    const __half* A;
    const __half* B;
    if (MODE == 0) {
        A = g_x;
        B = g_w1 + (size_t)ez * IDIM * HDIM;
    } else {
        A = g_mid + (size_t)ez * NTOK * IDIM;
        B = g_w2 + (size_t)ez * HDIM * IDIM;
    }

    uint32_t tiles = (smem_u32(dsm) + 1023u) & ~1023u;

    auto load_chunk = [&](int c, int b) {
        int kk = c * 64;
        uint32_t sA = tiles + b * STAGE;
        uint32_t sB = sA + A_BYTES;
        #pragma unroll
        for (int v = 0; v < 4; ++v) {              // 128 rows x 8 slots / 256 thr
            int idx = v * 256 + tid;
            int r = idx >> 3, c16 = idx & 7;
            cp_async16(sA + swz_row((uint32_t)r, (uint32_t)(c16 * 16)),
                       A + (size_t)(m0 + r) * K + kk + c16 * 8);
        }
        #pragma unroll
        for (int v = 0; v < 4; ++v) {
            int idx = v * 256 + tid;
            int r = idx >> 3, c16 = idx & 7;
            cp_async16(sB + swz_row((uint32_t)r, (uint32_t)(c16 * 16)),
                       B + (size_t)(n0 + r) * K + kk + c16 * 8);
        }
        asm volatile("cp.async.commit_group;\n" ::: "memory");
    };

    const int wm = (wid & 1) * 64;        // 2 warp-rows in M
    const int wn = (wid >> 1) * 32;       // 4 warp-cols in N

    float acc[4][4][4];                   // 64 regs
    #pragma unroll
    for (int mt = 0; mt < 4; ++mt)
        #pragma unroll
        for (int nt = 0; nt < 4; ++nt)
            #pragma unroll
            for (int q = 0; q < 4; ++q) acc[mt][nt][q] = 0.f;

    const uint32_t rA = (((uint32_t)lane >> 3) & 1u) * 8u + ((uint32_t)lane & 7u);
    const uint32_t kA0 = (((uint32_t)lane >> 4) & 1u) * 16u;
    const uint32_t rB = (((uint32_t)lane >> 4) & 1u) * 8u + ((uint32_t)lane & 7u);
    const uint32_t kB0 = (((uint32_t)lane >> 3) & 1u) * 16u;

    load_chunk(0, 0);
    load_chunk(1, 1);

    for (int c = 0; c < NC; ++c) {
        int b = c % NSTG;
        if (c + 1 < NC) asm volatile("cp.async.wait_group 1;\n" ::: "memory");
        else            asm volatile("cp.async.wait_group 0;\n" ::: "memory");
        // Single barrier: publishes chunk c AND retires reads of buffer (c+2)%3.
        __syncthreads();
        if (c + 2 < NC) load_chunk(c + 2, (c + 2) % NSTG);

        uint32_t sA = tiles + b * STAGE;
        uint32_t sB = sA + A_BYTES;

        #pragma unroll
        for (int ks = 0; ks < 4; ++ks) {
            uint32_t af[4][4];
            #pragma unroll
            for (int mt = 0; mt < 4; ++mt) {
                uint32_t row = (uint32_t)(wm + mt * 16) + rA;
                ldsm_x4(af[mt], sA + swz_row(row, (uint32_t)(ks * 32) + kA0));
            }
            uint32_t bfr[4][2];
            #pragma unroll
            for (int nt2 = 0; nt2 < 2; ++nt2) {
                uint32_t t[4];
                uint32_t row = (uint32_t)(wn + nt2 * 16) + rB;
                ldsm_x4(t, sB + swz_row(row, (uint32_t)(ks * 32) + kB0));
                bfr[2 * nt2][0] = t[0]; bfr[2 * nt2][1] = t[1];
                bfr[2 * nt2 + 1][0] = t[2]; bfr[2 * nt2 + 1][1] = t[3];
            }
            #pragma unroll
            for (int mt = 0; mt < 4; ++mt)
                #pragma unroll
                for (int nt = 0; nt < 4; ++nt)
                    mma16816(acc[mt][nt], af[mt], bfr[nt]);
        }
    }

    // ------------------------- epilogue -------------------------
    const int rbase = m0 + wm + (lane >> 2);
    const int cbase = n0 + wn + (lane & 3) * 2;

    if (MODE == 0) {
        __half* mid = g_mid + (size_t)ez * NTOK * IDIM;
        #pragma unroll
        for (int mt = 0; mt < 4; ++mt) {
            #pragma unroll
            for (int half = 0; half < 2; ++half) {
                int row = rbase + mt * 16 + half * 8;
                size_t base = (size_t)row * IDIM;
                #pragma unroll
                for (int nt = 0; nt < 4; ++nt) {
                    int col = cbase + nt * 8;
                    float v0 = acc[mt][nt][half * 2 + 0];
                    float v1 = acc[mt][nt][half * 2 + 1];
                    float g0 = 0.5f * v0 * (1.0f + erff(v0 * 0.70710678118654752f));
                    float g1 = 0.5f * v1 * (1.0f + erff(v1 * 0.70710678118654752f));
                    __half2 h2;
                    h2.x = __float2half_rn(g0);
                    h2.y = __float2half_rn(g1);
                    *(__half2*)(mid + base + col) = h2;
                }
            }
        }
    } else {
        float* part = g_part + (size_t)ez * NTOK * HDIM;
        #pragma unroll
        for (int mt = 0; mt < 4; ++mt) {
            #pragma unroll
            for (int half = 0; half < 2; ++half) {
                int row = rbase + mt * 16 + half * 8;
                float pw = g_probs[row * NEXP + ez];
                size_t base = (size_t)row * HDIM;
                #pragma unroll
                for (int nt = 0; nt < 4; ++nt) {
                    int col = cbase + nt * 8;
                    float2 v;
                    v.x = acc[mt][nt][half * 2 + 0] * pw;
                    v.y = acc[mt][nt][half * 2 + 1] * pw;
                    *(float2*)(part + base + col) = v;
                }
            }
        }
    }
}

// ------------------------- reduce: out = sum_e part[e] -------------------------
__global__ void moe_reduce_kernel(float* __restrict__ outp) {
    constexpr size_t N4 = (size_t)NTOK * HDIM / 4;
    size_t i = (size_t)blockIdx.x * blockDim.x + threadIdx.x;
    size_t stride = (size_t)gridDim.x * blockDim.x;
    for (; i < N4; i += stride) {
        const float4* p = (const float4*)g_part + i;
        float4 s = p[0];
        #pragma unroll
        for (int e = 1; e < NEXP; ++e) {
            float4 v = p[(size_t)e * N4];
            s.x += v.x; s.y += v.y; s.z += v.z; s.w += v.w;
        }
        ((float4*)outp)[i] = s;
    }
}

// ------------------------- host launch -------------------------
extern "C" void kernel_launch(void* const* d_in, const int* in_sizes, int n_in,
                              void* d_out, int out_size) {
    const float* hs = (const float*)d_in[0];
    const float* Wr = (const float*)d_in[1];
    const float* W1 = (const float*)d_in[2];
    const float* W2 = (const float*)d_in[3];
    float* outp = (float*)d_out;

    void *xp, *w1p, *w2p, *pp;
    cudaGetSymbolAddress(&xp, g_x);
    cudaGetSymbolAddress(&w1p, g_w1);
    cudaGetSymbolAddress(&w2p, g_w2);
    cudaGetSymbolAddress(&pp, g_probs);

    const int SMEM = 1024 + 3 * 32768;   // 99328/CTA, 2 CTA/SM
    cudaFuncSetAttribute((const void*)moe_gemm<0>,
                         cudaFuncAttributeMaxDynamicSharedMemorySize, SMEM);
    cudaFuncSetAttribute((const void*)moe_gemm<1>,
                         cudaFuncAttributeMaxDynamicSharedMemorySize, SMEM);

    moe_cvt3_kernel<<<4096, 256>>>(
        hs, (__half*)xp, (size_t)NTOK * HDIM / 8,
        W1, (__half*)w1p, (size_t)NEXP * IDIM * HDIM / 8,
        W2, (__half*)w2p, (size_t)NEXP * HDIM * IDIM / 8);
    moe_router_kernel<<<NTOK / 4, 128>>>(hs, Wr, (float*)pp);

    // GEMM1: all experts (grid 32x32x8 = 8192 CTAs)
    moe_gemm<0><<<dim3(NTOK / 128, IDIM / 128, NEXP), 256, SMEM>>>();
    // GEMM2: all experts (grid 32x8x8 = 2048 CTAs), fp32 partials
    moe_gemm<1><<<dim3(NTOK / 128, HDIM / 128, NEXP), 256, SMEM>>>();
    // Final combine
    moe_reduce_kernel<<<2048, 256>>>(outp);
}

// round 12
// speedup vs baseline: 1.0198x; 1.0198x over previous
#include <cuda_runtime.h>
#include <cuda_fp16.h>
#include <cstdint>
#include <cstddef>

#define NTOK 4096
#define HDIM 1024
#define IDIM 4096
#define NEXP 8

// ------------------------- scratch (static device, no allocs) -------------------------
__device__ __half g_x[(size_t)NTOK * HDIM];
__device__ __half g_w1[(size_t)NEXP * IDIM * HDIM];
__device__ __half g_w2[(size_t)NEXP * HDIM * IDIM];
__device__ __half g_mid[(size_t)NEXP * NTOK * IDIM];     // per-expert gelu output
__device__ float g_probs[NTOK * NEXP];

// ------------------------- PTX helpers -------------------------
__device__ __forceinline__ uint32_t smem_u32(const void* p) {
    uint32_t a;
    asm("{ .reg .u64 t; cvta.to.shared.u64 t, %1; cvt.u32.u64 %0, t; }" : "=r"(a) : "l"(p));
    return a;
}

__device__ __forceinline__ void cp_async16(uint32_t smem, const void* g) {
    asm volatile("cp.async.cg.shared.global [%0], [%1], 16;\n" :: "r"(smem), "l"(g));
}

// swizzle for 128B rows: off = row*128 + (colbyte ^ ((row&7)<<4))
__device__ __forceinline__ uint32_t swz_row(uint32_t row, uint32_t colbyte) {
    return row * 128u + (colbyte ^ ((row & 7u) << 4));
}

__device__ __forceinline__ void ldsm_x4(uint32_t (&r)[4], uint32_t addr) {
    asm volatile("ldmatrix.sync.aligned.m8n8.x4.shared.b16 {%0,%1,%2,%3}, [%4];"
                 : "=r"(r[0]), "=r"(r[1]), "=r"(r[2]), "=r"(r[3]) : "r"(addr));
}

__device__ __forceinline__ void mma16816(float (&d)[4], const uint32_t (&a)[4],
                                         const uint32_t (&b)[2]) {
    asm volatile(
        "mma.sync.aligned.m16n8k16.row.col.f32.f16.f16.f32 "
        "{%0,%1,%2,%3}, {%4,%5,%6,%7}, {%8,%9}, {%0,%1,%2,%3};"
        : "+f"(d[0]), "+f"(d[1]), "+f"(d[2]), "+f"(d[3])
        : "r"(a[0]), "r"(a[1]), "r"(a[2]), "r"(a[3]), "r"(b[0]), "r"(b[1]));
}

// ---------------- merged convert kernel: fp32 -> fp16 (x, W1, W2) + zero-init out --------
__global__ void moe_cvt3_kernel(const float* __restrict__ s0, __half* __restrict__ d0, size_t n0,
                                const float* __restrict__ s1, __half* __restrict__ d1, size_t n1,
                                const float* __restrict__ s2, __half* __restrict__ d2, size_t n2,
                                float* __restrict__ zout, size_t nz4) {
    size_t total = n0 + n1 + n2;
    size_t i = (size_t)blockIdx.x * blockDim.x + threadIdx.x;
    size_t stride = (size_t)gridDim.x * blockDim.x;
    // zero-init the output accumulator (float4 granules)
    for (size_t z = i; z < nz4; z += stride) {
        ((float4*)zout)[z] = make_float4(0.f, 0.f, 0.f, 0.f);
    }
    for (; i < total; i += stride) {
        const float* src;
        __half* dst;
        size_t j = i;
        if (j < n0) { src = s0; dst = d0; }
        else if (j < n0 + n1) { j -= n0; src = s1; dst = d1; }
        else { j -= n0 + n1; src = s2; dst = d2; }
        const float4* s = (const float4*)(src + j * 8);
        float4 a = s[0], b = s[1];
        union { __half h[8]; uint4 u; } H;
        H.h[0] = __float2half_rn(a.x); H.h[1] = __float2half_rn(a.y);
        H.h[2] = __float2half_rn(a.z); H.h[3] = __float2half_rn(a.w);
        H.h[4] = __float2half_rn(b.x); H.h[5] = __float2half_rn(b.y);
        H.h[6] = __float2half_rn(b.z); H.h[7] = __float2half_rn(b.w);
        *(uint4*)(dst + j * 8) = H.u;
    }
}

// ------------------------- router: logits -> softmax -> sort desc -------------------------
__global__ void moe_router_kernel(const float* __restrict__ hs, const float* __restrict__ Wr,
                                  float* __restrict__ probs) {
    int warp = threadIdx.x >> 5, lane = threadIdx.x & 31;
    int n = blockIdx.x * 4 + warp;
    if (n >= NTOK) return;
    const float* x = hs + (size_t)n * HDIM;
    float acc[NEXP];
    #pragma unroll
    for (int e = 0; e < NEXP; ++e) acc[e] = 0.f;
    for (int j = lane; j < HDIM; j += 32) {
        float xv = x[j];
        #pragma unroll
        for (int e = 0; e < NEXP; ++e) acc[e] += xv * Wr[e * HDIM + j];
    }
    #pragma unroll
    for (int off = 16; off; off >>= 1) {
        #pragma unroll
        for (int e = 0; e < NEXP; ++e)
            acc[e] += __shfl_down_sync(0xffffffffu, acc[e], off);
    }
    if (lane == 0) {
        float m = acc[0];
        #pragma unroll
        for (int e = 1; e < NEXP; ++e) m = fmaxf(m, acc[e]);
        float s = 0.f, p[NEXP];
        #pragma unroll
        for (int e = 0; e < NEXP; ++e) { p[e] = expf(acc[e] - m); s += p[e]; }
        float inv = 1.f / s;
        #pragma unroll
        for (int e = 0; e < NEXP; ++e) p[e] *= inv;
        #pragma unroll
        for (int i = 1; i < NEXP; ++i) {
            float key = p[i];
            int j = i - 1;
            while (j >= 0 && p[j] < key) { p[j + 1] = p[j]; --j; }
            p[j + 1] = key;
        }
        #pragma unroll
        for (int e = 0; e < NEXP; ++e) probs[n * NEXP + e] = p[e];
    }
}

// ------------------------- fp16 GEMM, 128x128 tile, 4 warps of 64x64 ---------------------
// 128 threads, 3-stage cp.async, 1 sync/chunk, 2 CTA/SM (measured-best engine, R10).
// MODE 0: K=HDIM;  A=x, B=w1[z];  mid[z] = fp16(gelu(D))
// MODE 1: K=IDIM;  A=mid[z], B=w2[z];  out += prob[m,z] * D  via atomicAdd (REDG)
template <int MODE>
__global__ void __launch_bounds__(128, 2) moe_gemm(float* __restrict__ outp) {
    constexpr int K = (MODE == 0) ? HDIM : IDIM;
    constexpr int MT = 128;
    constexpr int NT = 128;
    constexpr int A_BYTES = MT * 128;          // 16384
    constexpr int B_BYTES = NT * 128;          // 16384
    constexpr int STAGE = A_BYTES + B_BYTES;   // 32768
    constexpr int NSTG = 3;
    constexpr int NC = K / 64;

    extern __shared__ char dsm[];

    const int tid = threadIdx.x, wid = tid >> 5, lane = tid & 31;
    const int m0 = blockIdx.x * MT;
    const int n0 = blockIdx.y * NT;
    const int ez = blockIdx.z;

    const __half* A;
    const __half* B;
    if (MODE == 0) {
        A = g_x;
        B = g_w1 + (size_t)ez * IDIM * HDIM;
    } else {
        A = g_mid + (size_t)ez * NTOK * IDIM;
        B = g_w2 + (size_t)ez * HDIM * IDIM;
    }

    uint32_t tiles = (smem_u32(dsm) + 1023u) & ~1023u;

    auto load_chunk = [&](int c, int b) {
        int kk = c * 64;
        uint32_t sA = tiles + b * STAGE;
        uint32_t sB = sA + A_BYTES;
        #pragma unroll
        for (int v = 0; v < 8; ++v) {
            int idx = v * 128 + tid;
            int r = idx >> 3, c16 = idx & 7;
            cp_async16(sA + swz_row((uint32_t)r, (uint32_t)(c16 * 16)),
                       A + (size_t)(m0 + r) * K + kk + c16 * 8);
        }
        #pragma unroll
        for (int v = 0; v < 8; ++v) {
            int idx = v * 128 + tid;
            int r = idx >> 3, c16 = idx & 7;
            cp_async16(sB + swz_row((uint32_t)r, (uint32_t)(c16 * 16)),
                       B + (size_t)(n0 + r) * K + kk + c16 * 8);
        }
        asm volatile("cp.async.commit_group;\n" ::: "memory");
    };

    const int wm = (wid & 1) * 64;
    const int wn = (wid >> 1) * 64;

    float acc[4][8][4];
    #pragma unroll
    for (int mt = 0; mt < 4; ++mt)
        #pragma unroll
        for (int nt = 0; nt < 8; ++nt)
            #pragma unroll
            for (int q = 0; q < 4; ++q) acc[mt][nt][q] = 0.f;

    const uint32_t rA = (((uint32_t)lane >> 3) & 1u) * 8u + ((uint32_t)lane & 7u);
    const uint32_t kA0 = (((uint32_t)lane >> 4) & 1u) * 16u;
    const uint32_t rB = (((uint32_t)lane >> 4) & 1u) * 8u + ((uint32_t)lane & 7u);
    const uint32_t kB0 = (((uint32_t)lane >> 3) & 1u) * 16u;

    load_chunk(0, 0);
    load_chunk(1, 1);

    for (int c = 0; c < NC; ++c) {
        int b = c % NSTG;
        if (c + 1 < NC) asm volatile("cp.async.wait_group 1;\n" ::: "memory");
        else            asm volatile("cp.async.wait_group 0;\n" ::: "memory");
        // Single barrier: publishes chunk c AND retires reads of buffer (c+2)%3.
        __syncthreads();
        if (c + 2 < NC) load_chunk(c + 2, (c + 2) % NSTG);

        uint32_t sA = tiles + b * STAGE;
        uint32_t sB = sA + A_BYTES;

        #pragma unroll
        for (int ks = 0; ks < 4; ++ks) {
            uint32_t af[4][4];
            #pragma unroll
            for (int mt = 0; mt < 4; ++mt) {
                uint32_t row = (uint32_t)(wm + mt * 16) + rA;
                ldsm_x4(af[mt], sA + swz_row(row, (uint32_t)(ks * 32) + kA0));
            }
            uint32_t bfr[8][2];
            #pragma unroll
            for (int nt2 = 0; nt2 < 4; ++nt2) {
                uint32_t t[4];
                uint32_t row = (uint32_t)(wn + nt2 * 16) + rB;
                ldsm_x4(t, sB + swz_row(row, (uint32_t)(ks * 32) + kB0));
                bfr[2 * nt2][0] = t[0]; bfr[2 * nt2][1] = t[1];
                bfr[2 * nt2 + 1][0] = t[2]; bfr[2 * nt2 + 1][1] = t[3];
            }
            #pragma unroll
            for (int mt = 0; mt < 4; ++mt)
                #pragma unroll
                for (int nt = 0; nt < 8; ++nt)
                    mma16816(acc[mt][nt], af[mt], bfr[nt]);
        }
    }

    // ------------------------- epilogue -------------------------
    const int rbase = m0 + wm + (lane >> 2);
    const int cbase = n0 + wn + (lane & 3) * 2;

    if (MODE == 0) {
        __half* mid = g_mid + (size_t)ez * NTOK * IDIM;
        #pragma unroll
        for (int mt = 0; mt < 4; ++mt) {
            #pragma unroll
            for (int half = 0; half < 2; ++half) {
                int row = rbase + mt * 16 + half * 8;
                size_t base = (size_t)row * IDIM;
                #pragma unroll
                for (int nt = 0; nt < 8; ++nt) {
                    int col = cbase + nt * 8;
                    float v0 = acc[mt][nt][half * 2 + 0];
                    float v1 = acc[mt][nt][half * 2 + 1];
                    float g0 = 0.5f * v0 * (1.0f + erff(v0 * 0.70710678118654752f));
                    float g1 = 0.5f * v1 * (1.0f + erff(v1 * 0.70710678118654752f));
                    __half2 h2;
                    h2.x = __float2half_rn(g0);
                    h2.y = __float2half_rn(g1);
                    *(__half2*)(mid + base + col) = h2;
                }
            }
        }
    } else {
        #pragma unroll
        for (int mt = 0; mt < 4; ++mt) {
            #pragma unroll
            for (int half = 0; half < 2; ++half) {
                int row = rbase + mt * 16 + half * 8;
                float pw = g_probs[row * NEXP + ez];
                size_t base = (size_t)row * HDIM;
                #pragma unroll
                for (int nt = 0; nt < 8; ++nt) {
                    int col = cbase + nt * 8;
                    float* o = outp + base + col;
                    atomicAdd(o + 0, acc[mt][nt][half * 2 + 0] * pw);
                    atomicAdd(o + 1, acc[mt][nt][half * 2 + 1] * pw);
                }
            }
        }
    }
}

// ------------------------- host launch -------------------------
extern "C" void kernel_launch(void* const* d_in, const int* in_sizes, int n_in,
                              void* d_out, int out_size) {
    const float* hs = (const float*)d_in[0];
    const float* Wr = (const float*)d_in[1];
    const float* W1 = (const float*)d_in[2];
    const float* W2 = (const float*)d_in[3];
    float* outp = (float*)d_out;

    void *xp, *w1p, *w2p, *pp;
    cudaGetSymbolAddress(&xp, g_x);
    cudaGetSymbolAddress(&w1p, g_w1);
    cudaGetSymbolAddress(&w2p, g_w2);
    cudaGetSymbolAddress(&pp, g_probs);

    const int SMEM = 1024 + 3 * 32768;   // 99328/CTA, 2 CTA/SM
    cudaFuncSetAttribute((const void*)moe_gemm<0>,
                         cudaFuncAttributeMaxDynamicSharedMemorySize, SMEM);
    cudaFuncSetAttribute((const void*)moe_gemm<1>,
                         cudaFuncAttributeMaxDynamicSharedMemorySize, SMEM);

    // fp32->fp16 conversion for x, W1, W2 + zero-init of out (single launch)
    moe_cvt3_kernel<<<4096, 256>>>(
        hs, (__half*)xp, (size_t)NTOK * HDIM / 8,
        W1, (__half*)w1p, (size_t)NEXP * IDIM * HDIM / 8,
        W2, (__half*)w2p, (size_t)NEXP * HDIM * IDIM / 8,
        outp, (size_t)NTOK * HDIM / 4);
    moe_router_kernel<<<NTOK / 4, 128>>>(hs, Wr, (float*)pp);

    // GEMM1: all experts (grid 32x32x8 = 8192 CTAs, 27.7 waves at 2 CTA/SM)
    moe_gemm<0><<<dim3(NTOK / 128, IDIM / 128, NEXP), 128, SMEM>>>(nullptr);
    // GEMM2: all experts (grid 32x8x8 = 2048 CTAs), atomic accumulate into out
    moe_gemm<1><<<dim3(NTOK / 128, HDIM / 128, NEXP), 128, SMEM>>>(outp);
}

// round 13
// speedup vs baseline: 1.0325x; 1.0124x over previous
#include <cuda_runtime.h>
#include <cuda_fp16.h>
#include <cstdint>
#include <cstddef>

#define NTOK 4096
#define HDIM 1024
#define IDIM 4096
#define NEXP 8

// ------------------------- scratch (static device, no allocs) -------------------------
__device__ __half g_x[(size_t)NTOK * HDIM];
__device__ __half g_w1[(size_t)NEXP * IDIM * HDIM];
__device__ __half g_w2[(size_t)NEXP * HDIM * IDIM];
__device__ __half g_mid[(size_t)NEXP * NTOK * IDIM];     // per-expert gelu output
__device__ float g_probs[NTOK * NEXP];

// ------------------------- PTX helpers -------------------------
__device__ __forceinline__ uint32_t smem_u32(const void* p) {
    uint32_t a;
    asm("{ .reg .u64 t; cvta.to.shared.u64 t, %1; cvt.u32.u64 %0, t; }" : "=r"(a) : "l"(p));
    return a;
}

__device__ __forceinline__ void cp_async16(uint32_t smem, const void* g) {
    asm volatile("cp.async.cg.shared.global [%0], [%1], 16;\n" :: "r"(smem), "l"(g));
}

// swizzle for 128B rows: off = row*128 + (colbyte ^ ((row&7)<<4))
__device__ __forceinline__ uint32_t swz_row(uint32_t row, uint32_t colbyte) {
    return row * 128u + (colbyte ^ ((row & 7u) << 4));
}

__device__ __forceinline__ void ldsm_x4(uint32_t (&r)[4], uint32_t addr) {
    asm volatile("ldmatrix.sync.aligned.m8n8.x4.shared.b16 {%0,%1,%2,%3}, [%4];"
                 : "=r"(r[0]), "=r"(r[1]), "=r"(r[2]), "=r"(r[3]) : "r"(addr));
}

__device__ __forceinline__ void mma16816(float (&d)[4], const uint32_t (&a)[4],
                                         const uint32_t (&b)[2]) {
    asm volatile(
        "mma.sync.aligned.m16n8k16.row.col.f32.f16.f16.f32 "
        "{%0,%1,%2,%3}, {%4,%5,%6,%7}, {%8,%9}, {%0,%1,%2,%3};"
        : "+f"(d[0]), "+f"(d[1]), "+f"(d[2]), "+f"(d[3])
        : "r"(a[0]), "r"(a[1]), "r"(a[2]), "r"(a[3]), "r"(b[0]), "r"(b[1]));
}

// ---------------- merged convert kernel: fp32 -> fp16 (x, W1, W2) + zero-init out --------
__global__ void moe_cvt3_kernel(const float* __restrict__ s0, __half* __restrict__ d0, size_t n0,
                                const float* __restrict__ s1, __half* __restrict__ d1, size_t n1,
                                const float* __restrict__ s2, __half* __restrict__ d2, size_t n2,
                                float* __restrict__ zout, size_t nz4) {
    size_t total = n0 + n1 + n2;
    size_t i = (size_t)blockIdx.x * blockDim.x + threadIdx.x;
    size_t stride = (size_t)gridDim.x * blockDim.x;
    for (size_t z = i; z < nz4; z += stride) {
        ((float4*)zout)[z] = make_float4(0.f, 0.f, 0.f, 0.f);
    }
    for (; i < total; i += stride) {
        const float* src;
        __half* dst;
        size_t j = i;
        if (j < n0) { src = s0; dst = d0; }
        else if (j < n0 + n1) { j -= n0; src = s1; dst = d1; }
        else { j -= n0 + n1; src = s2; dst = d2; }
        const float4* s = (const float4*)(src + j * 8);
        float4 a = s[0], b = s[1];
        union { __half h[8]; uint4 u; } H;
        H.h[0] = __float2half_rn(a.x); H.h[1] = __float2half_rn(a.y);
        H.h[2] = __float2half_rn(a.z); H.h[3] = __float2half_rn(a.w);
        H.h[4] = __float2half_rn(b.x); H.h[5] = __float2half_rn(b.y);
        H.h[6] = __float2half_rn(b.z); H.h[7] = __float2half_rn(b.w);
        *(uint4*)(dst + j * 8) = H.u;
    }
}

// ------------------------- router: logits -> softmax -> sort desc -------------------------
__global__ void moe_router_kernel(const float* __restrict__ hs, const float* __restrict__ Wr,
                                  float* __restrict__ probs) {
    int warp = threadIdx.x >> 5, lane = threadIdx.x & 31;
    int n = blockIdx.x * 4 + warp;
    if (n >= NTOK) return;
    const float* x = hs + (size_t)n * HDIM;
    float acc[NEXP];
    #pragma unroll
    for (int e = 0; e < NEXP; ++e) acc[e] = 0.f;
    for (int j = lane; j < HDIM; j += 32) {
        float xv = x[j];
        #pragma unroll
        for (int e = 0; e < NEXP; ++e) acc[e] += xv * Wr[e * HDIM + j];
    }
    #pragma unroll
    for (int off = 16; off; off >>= 1) {
        #pragma unroll
        for (int e = 0; e < NEXP; ++e)
            acc[e] += __shfl_down_sync(0xffffffffu, acc[e], off);
    }
    if (lane == 0) {
        float m = acc[0];
        #pragma unroll
        for (int e = 1; e < NEXP; ++e) m = fmaxf(m, acc[e]);
        float s = 0.f, p[NEXP];
        #pragma unroll
        for (int e = 0; e < NEXP; ++e) { p[e] = expf(acc[e] - m); s += p[e]; }
        float inv = 1.f / s;
        #pragma unroll
        for (int e = 0; e < NEXP; ++e) p[e] *= inv;
        #pragma unroll
        for (int i = 1; i < NEXP; ++i) {
            float key = p[i];
            int j = i - 1;
            while (j >= 0 && p[j] < key) { p[j + 1] = p[j]; --j; }
            p[j + 1] = key;
        }
        #pragma unroll
        for (int e = 0; e < NEXP; ++e) probs[n * NEXP + e] = p[e];
    }
}

// ------------------------- fp16 GEMM, 128x128 tile, 4 warps of 64x64 ---------------------
// 128 threads, 3-stage cp.async, 1 sync/chunk, 2 CTA/SM.
// NEW: prefetch cp.async issue is interleaved into the 4 ks-iterations so LDGSTS
// issue cost (16 ops x rt8 = 128 cyc/warp) hides under HMMA instead of stalling
// the tensor pipe at the chunk boundary.
// MODE 0: K=HDIM;  A=x, B=w1[z];  mid[z] = fp16(gelu(D))
// MODE 1: K=IDIM;  A=mid[z], B=w2[z];  out += prob[m,z] * D  via atomicAdd (REDG)
template <int MODE>
__global__ void __launch_bounds__(128, 2) moe_gemm(float* __restrict__ outp) {
    constexpr int K = (MODE == 0) ? HDIM : IDIM;
    constexpr int MT = 128;
    constexpr int NT = 128;
    constexpr int A_BYTES = MT * 128;          // 16384
    constexpr int B_BYTES = NT * 128;          // 16384
    constexpr int STAGE = A_BYTES + B_BYTES;   // 32768
    constexpr int NSTG = 3;
    constexpr int NC = K / 64;

    extern __shared__ char dsm[];

    const int tid = threadIdx.x, wid = tid >> 5, lane = tid & 31;
    const int m0 = blockIdx.x * MT;
    const int n0 = blockIdx.y * NT;
    const int ez = blockIdx.z;

    const __half* A;
    const __half* B;
    if (MODE == 0) {
        A = g_x;
        B = g_w1 + (size_t)ez * IDIM * HDIM;
    } else {
        A = g_mid + (size_t)ez * NTOK * IDIM;
        B = g_w2 + (size_t)ez * HDIM * IDIM;
    }

    uint32_t tiles = (smem_u32(dsm) + 1023u) & ~1023u;

    // Full-chunk load (prologue only).
    auto load_chunk = [&](int c, int b) {
        int kk = c * 64;
        uint32_t sA = tiles + b * STAGE;
        uint32_t sB = sA + A_BYTES;
        #pragma unroll
        for (int v = 0; v < 8; ++v) {
            int idx = v * 128 + tid;
            int r = idx >> 3, c16 = idx & 7;
            cp_async16(sA + swz_row((uint32_t)r, (uint32_t)(c16 * 16)),
                       A + (size_t)(m0 + r) * K + kk + c16 * 8);
        }
        #pragma unroll
        for (int v = 0; v < 8; ++v) {
            int idx = v * 128 + tid;
            int r = idx >> 3, c16 = idx & 7;
            cp_async16(sB + swz_row((uint32_t)r, (uint32_t)(c16 * 16)),
                       B + (size_t)(n0 + r) * K + kk + c16 * 8);
        }
        asm volatile("cp.async.commit_group;\n" ::: "memory");
    };

    // Quarter-chunk load: part p issues A rows v=2p..2p+1 and B rows v=2p..2p+1.
    auto load_part = [&](int c, int b, int p) {
        int kk = c * 64;
        uint32_t sA = tiles + b * STAGE;
        uint32_t sB = sA + A_BYTES;
        #pragma unroll
        for (int v = 2 * 0; v < 2; ++v) {
            int idx = (2 * p + v) * 128 + tid;
            int r = idx >> 3, c16 = idx & 7;
            cp_async16(sA + swz_row((uint32_t)r, (uint32_t)(c16 * 16)),
                       A + (size_t)(m0 + r) * K + kk + c16 * 8);
        }
        #pragma unroll
        for (int v = 0; v < 2; ++v) {
            int idx = (2 * p + v) * 128 + tid;
            int r = idx >> 3, c16 = idx & 7;
            cp_async16(sB + swz_row((uint32_t)r, (uint32_t)(c16 * 16)),
                       B + (size_t)(n0 + r) * K + kk + c16 * 8);
        }
    };

    const int wm = (wid & 1) * 64;
    const int wn = (wid >> 1) * 64;

    float acc[4][8][4];
    #pragma unroll
    for (int mt = 0; mt < 4; ++mt)
        #pragma unroll
        for (int nt = 0; nt < 8; ++nt)
            #pragma unroll
            for (int q = 0; q < 4; ++q) acc[mt][nt][q] = 0.f;

    const uint32_t rA = (((uint32_t)lane >> 3) & 1u) * 8u + ((uint32_t)lane & 7u);
    const uint32_t kA0 = (((uint32_t)lane >> 4) & 1u) * 16u;
    const uint32_t rB = (((uint32_t)lane >> 4) & 1u) * 8u + ((uint32_t)lane & 7u);
    const uint32_t kB0 = (((uint32_t)lane >> 3) & 1u) * 16u;

    load_chunk(0, 0);
    load_chunk(1, 1);

    for (int c = 0; c < NC; ++c) {
        int b = c % NSTG;
        if (c + 1 < NC) asm volatile("cp.async.wait_group 1;\n" ::: "memory");
        else            asm volatile("cp.async.wait_group 0;\n" ::: "memory");
        // Single barrier: publishes chunk c AND retires reads of buffer (c+2)%3.
        __syncthreads();

        const bool pf = (c + 2 < NC);
        const int pb = (c + 2) % NSTG;

        uint32_t sA = tiles + b * STAGE;
        uint32_t sB = sA + A_BYTES;

        #pragma unroll
        for (int ks = 0; ks < 4; ++ks) {
            uint32_t af[4][4];
            #pragma unroll
            for (int mt = 0; mt < 4; ++mt) {
                uint32_t row = (uint32_t)(wm + mt * 16) + rA;
                ldsm_x4(af[mt], sA + swz_row(row, (uint32_t)(ks * 32) + kA0));
            }
            uint32_t bfr[8][2];
            #pragma unroll
            for (int nt2 = 0; nt2 < 4; ++nt2) {
                uint32_t t[4];
                uint32_t row = (uint32_t)(wn + nt2 * 16) + rB;
                ldsm_x4(t, sB + swz_row(row, (uint32_t)(ks * 32) + kB0));
                bfr[2 * nt2][0] = t[0]; bfr[2 * nt2][1] = t[1];
                bfr[2 * nt2 + 1][0] = t[2]; bfr[2 * nt2 + 1][1] = t[3];
            }
            // Interleaved prefetch: issue quarter of next-next chunk's loads here,
            // hidden under this ks-block's 32 HMMAs.
            if (pf) load_part(c + 2, pb, ks);
            #pragma unroll
            for (int mt = 0; mt < 4; ++mt)
                #pragma unroll
                for (int nt = 0; nt < 8; ++nt)
                    mma16816(acc[mt][nt], af[mt], bfr[nt]);
        }
        if (pf) asm volatile("cp.async.commit_group;\n" ::: "memory");
    }

    // ------------------------- epilogue -------------------------
    const int rbase = m0 + wm + (lane >> 2);
    const int cbase = n0 + wn + (lane & 3) * 2;

    if (MODE == 0) {
        __half* mid = g_mid + (size_t)ez * NTOK * IDIM;
        #pragma unroll
        for (int mt = 0; mt < 4; ++mt) {
            #pragma unroll
            for (int half = 0; half < 2; ++half) {
                int row = rbase + mt * 16 + half * 8;
                size_t base = (size_t)row * IDIM;
                #pragma unroll
                for (int nt = 0; nt < 8; ++nt) {
                    int col = cbase + nt * 8;
                    float v0 = acc[mt][nt][half * 2 + 0];
                    float v1 = acc[mt][nt][half * 2 + 1];
                    float g0 = 0.5f * v0 * (1.0f + erff(v0 * 0.70710678118654752f));
                    float g1 = 0.5f * v1 * (1.0f + erff(v1 * 0.70710678118654752f));
                    __half2 h2;
                    h2.x = __float2half_rn(g0);
                    h2.y = __float2half_rn(g1);
                    *(__half2*)(mid + base + col) = h2;
                }
            }
        }
    } else {
        #pragma unroll
        for (int mt = 0; mt < 4; ++mt) {
            #pragma unroll
            for (int half = 0; half < 2; ++half) {
                int row = rbase + mt * 16 + half * 8;
                float pw = g_probs[row * NEXP + ez];
                size_t base = (size_t)row * HDIM;
                #pragma unroll
                for (int nt = 0; nt < 8; ++nt) {
                    int col = cbase + nt * 8;
                    float* o = outp + base + col;
                    atomicAdd(o + 0, acc[mt][nt][half * 2 + 0] * pw);
                    atomicAdd(o + 1, acc[mt][nt][half * 2 + 1] * pw);
                }
            }
        }
    }
}

// ------------------------- host launch -------------------------
extern "C" void kernel_launch(void* const* d_in, const int* in_sizes, int n_in,
                              void* d_out, int out_size) {
    const float* hs = (const float*)d_in[0];
    const float* Wr = (const float*)d_in[1];
    const float* W1 = (const float*)d_in[2];
    const float* W2 = (const float*)d_in[3];
    float* outp = (float*)d_out;

    void *xp, *w1p, *w2p, *pp;
    cudaGetSymbolAddress(&xp, g_x);
    cudaGetSymbolAddress(&w1p, g_w1);
    cudaGetSymbolAddress(&w2p, g_w2);
    cudaGetSymbolAddress(&pp, g_probs);

    const int SMEM = 1024 + 3 * 32768;   // 99328/CTA, 2 CTA/SM
    cudaFuncSetAttribute((const void*)moe_gemm<0>,
                         cudaFuncAttributeMaxDynamicSharedMemorySize, SMEM);
    cudaFuncSetAttribute((const void*)moe_gemm<1>,
                         cudaFuncAttributeMaxDynamicSharedMemorySize, SMEM);

    moe_cvt3_kernel<<<4096, 256>>>(
        hs, (__half*)xp, (size_t)NTOK * HDIM / 8,
        W1, (__half*)w1p, (size_t)NEXP * IDIM * HDIM / 8,
        W2, (__half*)w2p, (size_t)NEXP * HDIM * IDIM / 8,
        outp, (size_t)NTOK * HDIM / 4);
    moe_router_kernel<<<NTOK / 4, 128>>>(hs, Wr, (float*)pp);

    // GEMM1: all experts (grid 32x32x8 = 8192 CTAs, 27.7 waves at 2 CTA/SM)
    moe_gemm<0><<<dim3(NTOK / 128, IDIM / 128, NEXP), 128, SMEM>>>(nullptr);
    // GEMM2: all experts (grid 32x8x8 = 2048 CTAs), atomic accumulate into out
    moe_gemm<1><<<dim3(NTOK / 128, HDIM / 128, NEXP), 128, SMEM>>>(outp);
}

// round 14
// speedup vs baseline: 1.0352x; 1.0026x over previous
#include <cuda_runtime.h>
#include <cuda_fp16.h>
#include <cstdint>
#include <cstddef>

#define NTOK 4096
#define HDIM 1024
#define IDIM 4096
#define NEXP 8

// ------------------------- scratch (static device, no allocs) -------------------------
__device__ __half g_x[(size_t)NTOK * HDIM];
__device__ __half g_w1[(size_t)NEXP * IDIM * HDIM];
__device__ __half g_w2[(size_t)NEXP * HDIM * IDIM];
__device__ __half g_mid[(size_t)NEXP * NTOK * IDIM];     // per-expert gelu output
__device__ float g_probs[NTOK * NEXP];

// ------------------------- PTX helpers -------------------------
__device__ __forceinline__ uint32_t smem_u32(const void* p) {
    uint32_t a;
    asm("{ .reg .u64 t; cvta.to.shared.u64 t, %1; cvt.u32.u64 %0, t; }" : "=r"(a) : "l"(p));
    return a;
}

__device__ __forceinline__ void cp_async16(uint32_t smem, const void* g) {
    asm volatile("cp.async.cg.shared.global [%0], [%1], 16;\n" :: "r"(smem), "l"(g));
}

// swizzle for 128B rows: off = row*128 + (colbyte ^ ((row&7)<<4))
__device__ __forceinline__ uint32_t swz_row(uint32_t row, uint32_t colbyte) {
    return row * 128u + (colbyte ^ ((row & 7u) << 4));
}

__device__ __forceinline__ void ldsm_x4(uint32_t (&r)[4], uint32_t addr) {
    asm volatile("ldmatrix.sync.aligned.m8n8.x4.shared.b16 {%0,%1,%2,%3}, [%4];"
                 : "=r"(r[0]), "=r"(r[1]), "=r"(r[2]), "=r"(r[3]) : "r"(addr));
}

__device__ __forceinline__ void mma16816(float (&d)[4], const uint32_t (&a)[4],
                                         const uint32_t (&b)[2]) {
    asm volatile(
        "mma.sync.aligned.m16n8k16.row.col.f32.f16.f16.f32 "
        "{%0,%1,%2,%3}, {%4,%5,%6,%7}, {%8,%9}, {%0,%1,%2,%3};"
        : "+f"(d[0]), "+f"(d[1]), "+f"(d[2]), "+f"(d[3])
        : "r"(a[0]), "r"(a[1]), "r"(a[2]), "r"(a[3]), "r"(b[0]), "r"(b[1]));
}

// -------- prep kernel: router (blocks < 512) + fp32->fp16 convert + zero-init out --------
__global__ void moe_prep_kernel(const float* __restrict__ hs, const float* __restrict__ Wr,
                                const float* __restrict__ W1, const float* __restrict__ W2,
                                __half* __restrict__ xp, __half* __restrict__ w1p,
                                __half* __restrict__ w2p,
                                float* __restrict__ probs, float* __restrict__ zout) {
    // --- router: blocks [0, 512), 8 warps -> 8 tokens per block ---
    if (blockIdx.x < 512) {
        int warp = threadIdx.x >> 5, lane = threadIdx.x & 31;
        int n = blockIdx.x * 8 + warp;
        const float* x = hs + (size_t)n * HDIM;
        float acc[NEXP];
        #pragma unroll
        for (int e = 0; e < NEXP; ++e) acc[e] = 0.f;
        for (int j = lane; j < HDIM; j += 32) {
            float xv = x[j];
            #pragma unroll
            for (int e = 0; e < NEXP; ++e) acc[e] += xv * Wr[e * HDIM + j];
        }
        #pragma unroll
        for (int off = 16; off; off >>= 1) {
            #pragma unroll
            for (int e = 0; e < NEXP; ++e)
                acc[e] += __shfl_down_sync(0xffffffffu, acc[e], off);
        }
        if (lane == 0) {
            float m = acc[0];
            #pragma unroll
            for (int e = 1; e < NEXP; ++e) m = fmaxf(m, acc[e]);
            float s = 0.f, p[NEXP];
            #pragma unroll
            for (int e = 0; e < NEXP; ++e) { p[e] = expf(acc[e] - m); s += p[e]; }
            float inv = 1.f / s;
            #pragma unroll
            for (int e = 0; e < NEXP; ++e) p[e] *= inv;
            #pragma unroll
            for (int i = 1; i < NEXP; ++i) {
                float key = p[i];
                int j = i - 1;
                while (j >= 0 && p[j] < key) { p[j + 1] = p[j]; --j; }
                p[j + 1] = key;
            }
            #pragma unroll
            for (int e = 0; e < NEXP; ++e) probs[n * NEXP + e] = p[e];
        }
    }

    // --- zero-init out + converts (all blocks, grid-stride) ---
    constexpr size_t n0 = (size_t)NTOK * HDIM / 8;
    constexpr size_t n1 = (size_t)NEXP * IDIM * HDIM / 8;
    constexpr size_t n2 = (size_t)NEXP * HDIM * IDIM / 8;
    constexpr size_t nz4 = (size_t)NTOK * HDIM / 4;
    size_t total = n0 + n1 + n2;
    size_t i = (size_t)blockIdx.x * blockDim.x + threadIdx.x;
    size_t stride = (size_t)gridDim.x * blockDim.x;
    for (size_t z = i; z < nz4; z += stride) {
        ((float4*)zout)[z] = make_float4(0.f, 0.f, 0.f, 0.f);
    }
    for (; i < total; i += stride) {
        const float* src;
        __half* dst;
        size_t j = i;
        if (j < n0) { src = hs; dst = xp; }
        else if (j < n0 + n1) { j -= n0; src = W1; dst = w1p; }
        else { j -= n0 + n1; src = W2; dst = w2p; }
        const float4* s = (const float4*)(src + j * 8);
        float4 a = s[0], b = s[1];
        union { __half h[8]; uint4 u; } H;
        H.h[0] = __float2half_rn(a.x); H.h[1] = __float2half_rn(a.y);
        H.h[2] = __float2half_rn(a.z); H.h[3] = __float2half_rn(a.w);
        H.h[4] = __float2half_rn(b.x); H.h[5] = __float2half_rn(b.y);
        H.h[6] = __float2half_rn(b.z); H.h[7] = __float2half_rn(b.w);
        *(uint4*)(dst + j * 8) = H.u;
    }
}

// ------------------------- fp16 GEMM, 128x128 tile, 4 warps of 64x64 ---------------------
// 128 threads, 3-stage cp.async, 1 sync/chunk, interleaved prefetch, 2 CTA/SM.
// PDL: consumer syncs on the previous kernel at entry; MODE 0 triggers early completion
// after its mid stores so GEMM2 CTAs can begin launching during GEMM1's tail wave.
// MODE 0: K=HDIM;  A=x, B=w1[z];  mid[z] = fp16(gelu(D))
// MODE 1: K=IDIM;  A=mid[z], B=w2[z];  out += prob[m,z] * D  via atomicAdd (REDG)
template <int MODE>
__global__ void __launch_bounds__(128, 2) moe_gemm(float* __restrict__ outp) {
    constexpr int K = (MODE == 0) ? HDIM : IDIM;
    constexpr int MT = 128;
    constexpr int NT = 128;
    constexpr int A_BYTES = MT * 128;          // 16384
    constexpr int B_BYTES = NT * 128;          // 16384
    constexpr int STAGE = A_BYTES + B_BYTES;   // 32768
    constexpr int NSTG = 3;
    constexpr int NC = K / 64;

    extern __shared__ char dsm[];

    const int tid = threadIdx.x, wid = tid >> 5, lane = tid & 31;
    const int m0 = blockIdx.x * MT;
    const int n0 = blockIdx.y * NT;
    const int ez = blockIdx.z;

    const __half* A;
    const __half* B;
    if (MODE == 0) {
        A = g_x;
        B = g_w1 + (size_t)ez * IDIM * HDIM;
    } else {
        A = g_mid + (size_t)ez * NTOK * IDIM;
        B = g_w2 + (size_t)ez * HDIM * IDIM;
    }

    uint32_t tiles = (smem_u32(dsm) + 1023u) & ~1023u;

    auto load_chunk = [&](int c, int b) {
        int kk = c * 64;
        uint32_t sA = tiles + b * STAGE;
        uint32_t sB = sA + A_BYTES;
        #pragma unroll
        for (int v = 0; v < 8; ++v) {
            int idx = v * 128 + tid;
            int r = idx >> 3, c16 = idx & 7;
            cp_async16(sA + swz_row((uint32_t)r, (uint32_t)(c16 * 16)),
                       A + (size_t)(m0 + r) * K + kk + c16 * 8);
        }
        #pragma unroll
        for (int v = 0; v < 8; ++v) {
            int idx = v * 128 + tid;
            int r = idx >> 3, c16 = idx & 7;
            cp_async16(sB + swz_row((uint32_t)r, (uint32_t)(c16 * 16)),
                       B + (size_t)(n0 + r) * K + kk + c16 * 8);
        }
        asm volatile("cp.async.commit_group;\n" ::: "memory");
    };

    // Quarter-chunk load: part p issues 2 A-vecs and 2 B-vecs.
    auto load_part = [&](int c, int b, int p) {
        int kk = c * 64;
        uint32_t sA = tiles + b * STAGE;
        uint32_t sB = sA + A_BYTES;
        #pragma unroll
        for (int v = 0; v < 2; ++v) {
            int idx = (2 * p + v) * 128 + tid;
            int r = idx >> 3, c16 = idx & 7;
            cp_async16(sA + swz_row((uint32_t)r, (uint32_t)(c16 * 16)),
                       A + (size_t)(m0 + r) * K + kk + c16 * 8);
        }
        #pragma unroll
        for (int v = 0; v < 2; ++v) {
            int idx = (2 * p + v) * 128 + tid;
            int r = idx >> 3, c16 = idx & 7;
            cp_async16(sB + swz_row((uint32_t)r, (uint32_t)(c16 * 16)),
                       B + (size_t)(n0 + r) * K + kk + c16 * 8);
        }
    };

    const int wm = (wid & 1) * 64;
    const int wn = (wid >> 1) * 64;

    float acc[4][8][4];
    #pragma unroll
    for (int mt = 0; mt < 4; ++mt)
        #pragma unroll
        for (int nt = 0; nt < 8; ++nt)
            #pragma unroll
            for (int q = 0; q < 4; ++q) acc[mt][nt][q] = 0.f;

    const uint32_t rA = (((uint32_t)lane >> 3) & 1u) * 8u + ((uint32_t)lane & 7u);
    const uint32_t kA0 = (((uint32_t)lane >> 4) & 1u) * 16u;
    const uint32_t rB = (((uint32_t)lane >> 4) & 1u) * 8u + ((uint32_t)lane & 7u);
    const uint32_t kB0 = (((uint32_t)lane >> 3) & 1u) * 16u;

    // PDL: wait for producer kernel's data (prep for MODE 0; gemm<0> for MODE 1)
    // before the first dependent global read. Prologue above overlaps the tail.
    cudaGridDependencySynchronize();

    load_chunk(0, 0);
    load_chunk(1, 1);

    for (int c = 0; c < NC; ++c) {
        int b = c % NSTG;
        if (c + 1 < NC) asm volatile("cp.async.wait_group 1;\n" ::: "memory");
        else            asm volatile("cp.async.wait_group 0;\n" ::: "memory");
        // Single barrier: publishes chunk c AND retires reads of buffer (c+2)%3.
        __syncthreads();

        const bool pf = (c + 2 < NC);
        const int pb = (c + 2) % NSTG;

        uint32_t sA = tiles + b * STAGE;
        uint32_t sB = sA + A_BYTES;

        #pragma unroll
        for (int ks = 0; ks < 4; ++ks) {
            uint32_t af[4][4];
            #pragma unroll
            for (int mt = 0; mt < 4; ++mt) {
                uint32_t row = (uint32_t)(wm + mt * 16) + rA;
                ldsm_x4(af[mt], sA + swz_row(row, (uint32_t)(ks * 32) + kA0));
            }
            uint32_t bfr[8][2];
            #pragma unroll
            for (int nt2 = 0; nt2 < 4; ++nt2) {
                uint32_t t[4];
                uint32_t row = (uint32_t)(wn + nt2 * 16) + rB;
                ldsm_x4(t, sB + swz_row(row, (uint32_t)(ks * 32) + kB0));
                bfr[2 * nt2][0] = t[0]; bfr[2 * nt2][1] = t[1];
                bfr[2 * nt2 + 1][0] = t[2]; bfr[2 * nt2 + 1][1] = t[3];
            }
            if (pf) load_part(c + 2, pb, ks);
            #pragma unroll
            for (int mt = 0; mt < 4; ++mt)
                #pragma unroll
                for (int nt = 0; nt < 8; ++nt)
                    mma16816(acc[mt][nt], af[mt], bfr[nt]);
        }
        if (pf) asm volatile("cp.async.commit_group;\n" ::: "memory");
    }

    // ------------------------- epilogue -------------------------
    const int rbase = m0 + wm + (lane >> 2);
    const int cbase = n0 + wn + (lane & 3) * 2;

    if (MODE == 0) {
        __half* mid = g_mid + (size_t)ez * NTOK * IDIM;
        #pragma unroll
        for (int mt = 0; mt < 4; ++mt) {
            #pragma unroll
            for (int half = 0; half < 2; ++half) {
                int row = rbase + mt * 16 + half * 8;
                size_t base = (size_t)row * IDIM;
                #pragma unroll
                for (int nt = 0; nt < 8; ++nt) {
                    int col = cbase + nt * 8;
                    float v0 = acc[mt][nt][half * 2 + 0];
                    float v1 = acc[mt][nt][half * 2 + 1];
                    float g0 = 0.5f * v0 * (1.0f + erff(v0 * 0.70710678118654752f));
                    float g1 = 0.5f * v1 * (1.0f + erff(v1 * 0.70710678118654752f));
                    __half2 h2;
                    h2.x = __float2half_rn(g0);
                    h2.y = __float2half_rn(g1);
                    *(__half2*)(mid + base + col) = h2;
                }
            }
        }
        // PDL: publish mid stores, then signal early completion so the
        // dependent GEMM2 grid starts launching during our tail wave.
        __threadfence();
        cudaTriggerProgrammaticLaunchCompletion();
    } else {
        #pragma unroll
        for (int mt = 0; mt < 4; ++mt) {
            #pragma unroll
            for (int half = 0; half < 2; ++half) {
                int row = rbase + mt * 16 + half * 8;
                float pw = g_probs[row * NEXP + ez];
                size_t base = (size_t)row * HDIM;
                #pragma unroll
                for (int nt = 0; nt < 8; ++nt) {
                    int col = cbase + nt * 8;
                    float* o = outp + base + col;
                    atomicAdd(o + 0, acc[mt][nt][half * 2 + 0] * pw);
                    atomicAdd(o + 1, acc[mt][nt][half * 2 + 1] * pw);
                }
            }
        }
    }
}

// ------------------------- host launch -------------------------
extern "C" void kernel_launch(void* const* d_in, const int* in_sizes, int n_in,
                              void* d_out, int out_size) {
    const float* hs = (const float*)d_in[0];
    const float* Wr = (const float*)d_in[1];
    const float* W1 = (const float*)d_in[2];
    const float* W2 = (const float*)d_in[3];
    float* outp = (float*)d_out;

    void *xp, *w1p, *w2p, *pp;
    cudaGetSymbolAddress(&xp, g_x);
    cudaGetSymbolAddress(&w1p, g_w1);
    cudaGetSymbolAddress(&w2p, g_w2);
    cudaGetSymbolAddress(&pp, g_probs);

    const int SMEM = 1024 + 3 * 32768;   // 99328/CTA, 2 CTA/SM
    cudaFuncSetAttribute((const void*)moe_gemm<0>,
                         cudaFuncAttributeMaxDynamicSharedMemorySize, SMEM);
    cudaFuncSetAttribute((const void*)moe_gemm<1>,
                         cudaFuncAttributeMaxDynamicSharedMemorySize, SMEM);

    // prep: router + converts + zero-init (one launch)
    moe_prep_kernel<<<5120, 256>>>(hs, Wr, W1, W2,
                                   (__half*)xp, (__half*)w1p, (__half*)w2p,
                                   (float*)pp, outp);

    // PDL launch attribute: allow overlap with preceding kernel's tail.
    cudaLaunchAttribute attrs[1];
    attrs[0].id = cudaLaunchAttributeProgrammaticStreamSerialization;
    attrs[0].val.programmaticStreamSerializationAllowed = 1;

    // GEMM1: all experts (grid 32x32x8 = 8192 CTAs, 27.7 waves at 2 CTA/SM)
    {
        cudaLaunchConfig_t cfg = {};
        cfg.gridDim = dim3(NTOK / 128, IDIM / 128, NEXP);
        cfg.blockDim = dim3(128, 1, 1);
        cfg.dynamicSmemBytes = SMEM;
        cfg.attrs = attrs;
        cfg.numAttrs = 1;
        cudaLaunchKernelEx(&cfg, moe_gemm<0>, (float*)nullptr);
    }
    // GEMM2: all experts (grid 32x8x8 = 2048 CTAs), atomic accumulate into out
    {
        cudaLaunchConfig_t cfg = {};
        cfg.gridDim = dim3(NTOK / 128, HDIM / 128, NEXP);
        cfg.blockDim = dim3(128, 1, 1);
        cfg.dynamicSmemBytes = SMEM;
        cfg.attrs = attrs;
        cfg.numAttrs = 1;
        cudaLaunchKernelEx(&cfg, moe_gemm<1>, outp);
    }
}